// round 4
// baseline (speedup 1.0000x reference)
#include <cuda_runtime.h>

#define NTH   512
#define NST   32
#define SCAP  (NTH * NST)        // 16384 states capacity
#define TMAX  64
#define CH    256                // cand-history stride (>= 4*T)
#define SPCAP 2048
#define SPT   4                  // sparse entries per thread
#define SENT  (-1e38f)
#define NEGV  (-1e30f)
#define NFMAX 6000

// cand history: per frame, the 4*T values v_t[prev_last[...]] needed to
// recompute argmax during backtrace. 6000*256*4B = 6.1MB scratch.
__device__ float g_hist[NFMAX * CH];

struct SM {
    float vraw[SCAP + 4];        // V = vraw+4; vraw[3] holds v[-1] = NEG
    float lt[TMAX * TMAX];       // log_trans (one beat slice; identical across beats)
    float cand[4 * 64];          // staged cand, layout [b][64]
    float dens[4];               // d0,d1,d2 for current frame
    int   plsm[256];             // prev_last flat (4*T)
    int   slist[SPCAP];          // sparse exception states: (s<<2)|code
    int   scount;
    int   pad0[3];
    unsigned short ptab[SCAP];   // (fidx+1)<<2 | ptrcode  (fidx 0 => not a first state)
    float rv[NTH];               // final argmax partials
    int   ri[NTH];
};

__global__ void __launch_bounds__(NTH, 1)
dbn_viterbi_kernel(const float* __restrict__ acts,
                   const float* __restrict__ log_trans,
                   const int*   __restrict__ prev_last,
                   const int*   __restrict__ first_states,
                   const int*   __restrict__ pointer,
                   float*       __restrict__ out,
                   int S, int T, int NF, int out_size)
{
    extern __shared__ unsigned char smraw[];
    SM* sm = reinterpret_cast<SM*>(smraw);
    float* V = sm->vraw + 4;

    const int tid  = threadIdx.x;
    const int lane = tid & 31;
    const int NT4  = 4 * T;          // number of (beat, tempo) segments (<=256)
    const int s0   = tid * NST;      // this thread's dense state segment

    // ---------------- one-time setup ----------------
    {
        float v0 = -logf((float)S);
        for (int s = tid; s < SCAP; s += NTH) V[s] = v0;
        if (tid == 0) V[-1] = NEGV;
        for (int idx = tid; idx < T * T; idx += NTH) sm->lt[idx] = log_trans[idx];
        for (int idx = tid; idx < 4 * 64; idx += NTH) sm->cand[idx] = 0.f;
        for (int s = tid; s < SCAP; s += NTH)
            sm->ptab[s] = (s < S) ? (unsigned short)(pointer[s] & 3) : (unsigned short)0;
        if (tid < NT4) sm->plsm[tid] = prev_last[tid];
        if (tid == 0) sm->scount = 0;
    }
    __syncthreads();  // lt / ptab-base ready

    // mark first states in ptab (distinct addresses, no race)
    if (tid < NT4) {
        int fs = first_states[tid];
        sm->ptab[fs] = (unsigned short)(sm->ptab[fs] | ((tid + 1) << 2));
    }

    // transition-role setup: lane pair (task, chunk c in {0,1}); i = c*32 + k
    const bool isA = (tid < 2 * NT4);
    int  a_b = 0, a_c = 0, a_faddr = 0;
    bool a_beat0 = false;
    float ltreg[32];
    if (isA) {
        int task = tid >> 1;
        a_c = tid & 1;
        a_b = task / T;
        int a_j = task - a_b * T;
        a_faddr = first_states[task];
        a_beat0 = (a_b == 0);
        #pragma unroll
        for (int k = 0; k < 32; k++) {
            int i = a_c * 32 + k;
            ltreg[k] = (i < T) ? sm->lt[i * T + a_j] : SENT;
        }
    } else {
        #pragma unroll
        for (int k = 0; k < 32; k++) ltreg[k] = SENT;
    }

    // staging role
    int my_pl = 0, my_candoff = 0;
    if (tid < NT4) {
        my_pl = sm->plsm[tid];
        int b = tid / T, i = tid - b * T;
        my_candoff = b * 64 + i;
    }
    __syncthreads();  // first flags in ptab complete

    // sparse exception list: ptr != 0 and not a first state
    {
        for (int k = 0; k < NST; k++) {
            int s = s0 + k;
            if (s < S) {
                unsigned short p = sm->ptab[s];
                if ((p & 3) != 0 && (p >> 2) == 0) {
                    int pos = atomicAdd(&sm->scount, 1);
                    if (pos < SPCAP) sm->slist[pos] = (s << 2) | (p & 3);
                }
            }
        }
    }
    __syncthreads();

    int scount = min(sm->scount, SPCAP);
    int sp_s[SPT]; int sp_c[SPT];
    #pragma unroll
    for (int e = 0; e < SPT; e++) {
        int idx = tid + e * NTH;
        if (idx < scount) { int v = sm->slist[idx]; sp_s[e] = v >> 2; sp_c[e] = v & 3; }
        else              { sp_s[e] = -1;           sp_c[e] = 0; }
    }

    // ---------------- forward Viterbi ----------------
    for (int t = 0; t < NF; t++) {
        __syncthreads();   // barA: v_t complete

        // phase L: loads (reads of v_t only)
        if (tid == 0) {
            float ab = acts[2 * t], ad = acts[2 * t + 1];
            sm->dens[0] = logf((1.f - ab - ad) / 15.f);
            sm->dens[1] = logf(ab);
            sm->dens[2] = logf(ad);
        }
        if (tid < NT4) {
            float c = V[my_pl];
            sm->cand[my_candoff] = c;
            g_hist[t * CH + tid] = c;      // backtrace history
        }
        float r[NST];
        #pragma unroll
        for (int g = 0; g < NST / 4; g++)
            *(float4*)(r + 4 * g) = *(const float4*)(V + s0 + 4 * g);
        float vm1 = V[s0 - 1];
        float sprev[SPT];
        #pragma unroll
        for (int e = 0; e < SPT; e++)
            sprev[e] = (sp_s[e] >= 0) ? V[sp_s[e] - 1] : 0.f;

        __syncthreads();   // bar2: all reads of v_t done; writes may begin
        float d0 = sm->dens[0], d1 = sm->dens[1], d2 = sm->dens[2];

        // dense: v_{t+1}[s] = v_t[s-1] + d0  (exception slots get garbage; fixed below)
        #pragma unroll
        for (int k = NST - 1; k >= 1; k--) r[k] = r[k - 1] + d0;
        r[0] = vm1 + d0;
        #pragma unroll
        for (int g = 0; g < NST / 4; g++)
            *(float4*)(V + s0 + 4 * g) = *(float4*)(r + 4 * g);

        // transition max (registers + cand broadcast; no argmax needed here)
        float acc = SENT;
        if (isA) {
            const float* cb = sm->cand + a_b * 64 + a_c * 32;
            #pragma unroll
            for (int k = 0; k < 32; k++)
                acc = fmaxf(acc, cb[k] + ltreg[k]);
        }

        __syncthreads();   // bar3: dense stores done; fixups now
        float other = __shfl_down_sync(0xffffffffu, acc, 1);
        if (isA && a_c == 0) {
            float best = fmaxf(acc, other);
            V[a_faddr] = best + (a_beat0 ? d2 : d1);
        }
        #pragma unroll
        for (int e = 0; e < SPT; e++)
            if (sp_s[e] >= 0)
                V[sp_s[e]] = sprev[e] + (sp_c[e] == 2 ? d2 : d1);
    }
    __syncthreads();

    // ---------------- final argmax (first occurrence) ----------------
    {
        float bv = SENT; int bi = 0;
        #pragma unroll
        for (int k = 0; k < NST; k++) {
            int s = s0 + k;
            if (s < S) {
                float x = V[s];
                if (x > bv) { bv = x; bi = s; }
            }
        }
        sm->rv[tid] = bv; sm->ri[tid] = bi;
    }
    __syncthreads();

    if (tid < 32) {
        float bv = SENT; int bi = 0x7fffffff;
        for (int m = lane; m < NTH; m += 32) {
            float x = sm->rv[m]; int ii = sm->ri[m];
            if (x > bv || (x == bv && ii < bi)) { bv = x; bi = ii; }
        }
        #pragma unroll
        for (int off = 16; off; off >>= 1) {
            float xv = __shfl_down_sync(0xffffffffu, bv, off);
            int   xi = __shfl_down_sync(0xffffffffu, bi, off);
            if (xv > bv || (xv == bv && xi < bi)) { bv = xv; bi = xi; }
        }
        bi = __shfl_sync(0xffffffffu, bi, 0);
        bv = __shfl_sync(0xffffffffu, bv, 0);
        if (lane == 0) {
            if (out_size > NF) out[NF] = bv;       // logp
            out[NF - 1] = (float)bi;               // path[NF-1]
        }

        // ---------------- backtrace (warp 0) ----------------
        int s = bi, tt = NF - 1;
        while (tt > 0) {
            unsigned short pt = sm->ptab[s];
            int f = pt >> 2;
            if (f) {
                // first state: recompute argmax_i (first occurrence), exact-bit
                f -= 1;
                int b = f / T, j = f - b * T;
                float bvv = SENT; int bii = 0x7fffffff;
                for (int i = lane; i < T; i += 32) {
                    float x = g_hist[tt * CH + b * T + i] + sm->lt[i * T + j];
                    if (x > bvv || (x == bvv && i < bii)) { bvv = x; bii = i; }
                }
                #pragma unroll
                for (int off = 16; off; off >>= 1) {
                    float xv = __shfl_down_sync(0xffffffffu, bvv, off);
                    int   xi = __shfl_down_sync(0xffffffffu, bii, off);
                    if (xv > bvv || (xv == bvv && xi < bii)) { bvv = xv; bii = xi; }
                }
                bii = __shfl_sync(0xffffffffu, bii, 0);
                int p = sm->plsm[b * T + bii];
                if (lane == 0) out[tt - 1] = (float)p;
                s = p; tt -= 1;
            } else {
                // emit a chain run (up to 32 entries at once)
                int ss = s - 1 - lane;
                bool isf = (ss >= 0) ? ((sm->ptab[ss] >> 2) != 0) : true;
                unsigned flags = __ballot_sync(0xffffffffu, isf);
                int cnt = flags ? __ffs(flags) : 32;   // include the first-state entry
                cnt = min(cnt, tt);
                if (lane < cnt) out[tt - 1 - lane] = (float)(s - 1 - lane);
                s -= cnt; tt -= cnt;
            }
        }
    }
}

extern "C" void kernel_launch(void* const* d_in, const int* in_sizes, int n_in,
                              void* d_out, int out_size)
{
    const float* acts = (const float*)d_in[0];
    const float* lt   = (const float*)d_in[1];
    const int*   pl   = (const int*)d_in[2];
    const int*   fs   = (const int*)d_in[3];
    const int*   ptr  = (const int*)d_in[4];

    int NF = in_sizes[0] / 2;          // activations (NF, 2)
    int T  = in_sizes[2] / 4;          // prev_last (4, T)
    int S  = in_sizes[4];              // pointer (S,)
    if (NF > NFMAX) NF = NFMAX;

    size_t smem = sizeof(SM);
    static bool attr_set = false;
    if (!attr_set) {
        cudaFuncSetAttribute(dbn_viterbi_kernel,
                             cudaFuncAttributeMaxDynamicSharedMemorySize, (int)smem);
        attr_set = true;
    }
    dbn_viterbi_kernel<<<1, NTH, smem>>>(acts, lt, pl, fs, ptr,
                                         (float*)d_out, S, T, NF, out_size);
}

// round 5
// speedup vs baseline: 1.0047x; 1.0047x over previous
#include <cuda_runtime.h>

#define NTH   512
#define NST   32
#define SCAP  (NTH * NST)        // 16384 states capacity
#define TMAX  64
#define CH    256                // cand-history stride (>= 4*T)
#define SPCAP 2048
#define SPT   4                  // sparse entries per thread
#define SENT  (-1e38f)
#define NEGV  (-1e30f)
#define NFMAX 6000

// cand history: per frame, the 4*T values v_t[prev_last[...]] needed to
// recompute argmax during backtrace. 6000*256*4B = 6.1MB scratch.
__device__ float g_hist[NFMAX * CH];

struct SM {
    float vraw[SCAP + 4];        // V = vraw+4; vraw[3] holds v[-1] = NEG
    float lt[TMAX * TMAX];       // log_trans (one beat slice; identical across beats)
    float cand[4 * 64];          // staged cand, layout [b][64]
    float dens[4];               // d0,d1,d2 for current frame
    int   plsm[256];             // prev_last flat (4*T)
    int   slist[SPCAP];          // sparse exception states: (s<<2)|code
    int   scount;
    int   pad0[3];
    unsigned short ptab[SCAP];   // (fidx+1)<<2 | ptrcode  (fidx 0 => not a first state)
    float rv[NTH];               // final argmax partials
    int   ri[NTH];
};

__global__ void __launch_bounds__(NTH, 1)
dbn_viterbi_kernel(const float* __restrict__ acts,
                   const float* __restrict__ log_trans,
                   const int*   __restrict__ prev_last,
                   const int*   __restrict__ first_states,
                   const int*   __restrict__ pointer,
                   float*       __restrict__ out,
                   int S, int T, int NF, int out_size)
{
    extern __shared__ unsigned char smraw[];
    SM* sm = reinterpret_cast<SM*>(smraw);
    float* V = sm->vraw + 4;

    const int tid  = threadIdx.x;
    const int lane = tid & 31;
    const int NT4  = 4 * T;          // number of (beat, tempo) segments (<=256)
    const int s0   = tid * NST;      // this thread's dense state segment

    // ---------------- one-time setup ----------------
    {
        float v0 = -logf((float)S);
        for (int s = tid; s < SCAP; s += NTH) V[s] = v0;
        if (tid == 0) V[-1] = NEGV;
        for (int idx = tid; idx < T * T; idx += NTH) sm->lt[idx] = log_trans[idx];
        for (int idx = tid; idx < 4 * 64; idx += NTH) sm->cand[idx] = 0.f;
        for (int s = tid; s < SCAP; s += NTH)
            sm->ptab[s] = (s < S) ? (unsigned short)(pointer[s] & 3) : (unsigned short)0;
        if (tid < NT4) sm->plsm[tid] = prev_last[tid];
        if (tid == 0) sm->scount = 0;
    }
    __syncthreads();  // lt / ptab-base ready

    // mark first states in ptab (distinct addresses, no race)
    if (tid < NT4) {
        int fs = first_states[tid];
        sm->ptab[fs] = (unsigned short)(sm->ptab[fs] | ((tid + 1) << 2));
    }

    // transition-role setup: lane pair (task, chunk c in {0,1}); i = c*32 + k
    const bool isA = (tid < 2 * NT4);
    int  a_b = 0, a_c = 0, a_faddr = 0;
    bool a_beat0 = false;
    float ltreg[32];
    if (isA) {
        int task = tid >> 1;
        a_c = tid & 1;
        a_b = task / T;
        int a_j = task - a_b * T;
        a_faddr = first_states[task];
        a_beat0 = (a_b == 0);
        #pragma unroll
        for (int k = 0; k < 32; k++) {
            int i = a_c * 32 + k;
            ltreg[k] = (i < T) ? sm->lt[i * T + a_j] : SENT;
        }
    } else {
        #pragma unroll
        for (int k = 0; k < 32; k++) ltreg[k] = SENT;
    }

    // staging role
    int my_pl = 0, my_candoff = 0;
    if (tid < NT4) {
        my_pl = sm->plsm[tid];
        int b = tid / T, i = tid - b * T;
        my_candoff = b * 64 + i;
    }
    __syncthreads();  // first flags in ptab complete

    // sparse exception list: ptr != 0 and not a first state
    {
        for (int k = 0; k < NST; k++) {
            int s = s0 + k;
            if (s < S) {
                unsigned short p = sm->ptab[s];
                if ((p & 3) != 0 && (p >> 2) == 0) {
                    int pos = atomicAdd(&sm->scount, 1);
                    if (pos < SPCAP) sm->slist[pos] = (s << 2) | (p & 3);
                }
            }
        }
    }
    __syncthreads();

    int scount = min(sm->scount, SPCAP);
    int sp_s[SPT]; int sp_c[SPT];
    #pragma unroll
    for (int e = 0; e < SPT; e++) {
        int idx = tid + e * NTH;
        if (idx < scount) { int v = sm->slist[idx]; sp_s[e] = v >> 2; sp_c[e] = v & 3; }
        else              { sp_s[e] = -1;           sp_c[e] = 0; }
    }

    // ---------------- forward Viterbi ----------------
    for (int t = 0; t < NF; t++) {
        __syncthreads();   // barA: v_t complete

        // phase L: loads (reads of v_t only)
        if (tid == 0) {
            float ab = acts[2 * t], ad = acts[2 * t + 1];
            sm->dens[0] = logf((1.f - ab - ad) / 15.f);
            sm->dens[1] = logf(ab);
            sm->dens[2] = logf(ad);
        }
        if (tid < NT4) {
            float c = V[my_pl];
            sm->cand[my_candoff] = c;
            g_hist[t * CH + tid] = c;      // backtrace history
        }
        float r[NST];
        #pragma unroll
        for (int g = 0; g < NST / 4; g++)
            *(float4*)(r + 4 * g) = *(const float4*)(V + s0 + 4 * g);
        float vm1 = V[s0 - 1];
        float sprev[SPT];
        #pragma unroll
        for (int e = 0; e < SPT; e++)
            sprev[e] = (sp_s[e] >= 0) ? V[sp_s[e] - 1] : 0.f;

        __syncthreads();   // bar2: all reads of v_t done; writes may begin
        float d0 = sm->dens[0], d1 = sm->dens[1], d2 = sm->dens[2];

        // dense: v_{t+1}[s] = v_t[s-1] + d0  (exception slots get garbage; fixed below)
        #pragma unroll
        for (int k = NST - 1; k >= 1; k--) r[k] = r[k - 1] + d0;
        r[0] = vm1 + d0;
        #pragma unroll
        for (int g = 0; g < NST / 4; g++)
            *(float4*)(V + s0 + 4 * g) = *(float4*)(r + 4 * g);

        // transition max (registers + cand broadcast; no argmax needed here)
        float acc = SENT;
        if (isA) {
            const float* cb = sm->cand + a_b * 64 + a_c * 32;
            #pragma unroll
            for (int k = 0; k < 32; k++)
                acc = fmaxf(acc, cb[k] + ltreg[k]);
        }

        __syncthreads();   // bar3: dense stores done; fixups now
        float other = __shfl_down_sync(0xffffffffu, acc, 1);
        if (isA && a_c == 0) {
            float best = fmaxf(acc, other);
            V[a_faddr] = best + (a_beat0 ? d2 : d1);
        }
        #pragma unroll
        for (int e = 0; e < SPT; e++)
            if (sp_s[e] >= 0)
                V[sp_s[e]] = sprev[e] + (sp_c[e] == 2 ? d2 : d1);
    }
    __syncthreads();

    // ---------------- final argmax (first occurrence) ----------------
    {
        float bv = SENT; int bi = 0;
        #pragma unroll
        for (int k = 0; k < NST; k++) {
            int s = s0 + k;
            if (s < S) {
                float x = V[s];
                if (x > bv) { bv = x; bi = s; }
            }
        }
        sm->rv[tid] = bv; sm->ri[tid] = bi;
    }
    __syncthreads();

    if (tid < 32) {
        float bv = SENT; int bi = 0x7fffffff;
        for (int m = lane; m < NTH; m += 32) {
            float x = sm->rv[m]; int ii = sm->ri[m];
            if (x > bv || (x == bv && ii < bi)) { bv = x; bi = ii; }
        }
        #pragma unroll
        for (int off = 16; off; off >>= 1) {
            float xv = __shfl_down_sync(0xffffffffu, bv, off);
            int   xi = __shfl_down_sync(0xffffffffu, bi, off);
            if (xv > bv || (xv == bv && xi < bi)) { bv = xv; bi = xi; }
        }
        bi = __shfl_sync(0xffffffffu, bi, 0);
        bv = __shfl_sync(0xffffffffu, bv, 0);
        if (lane == 0) {
            if (out_size > NF) out[NF] = bv;       // logp
            out[NF - 1] = (float)bi;               // path[NF-1]
        }

        // ---------------- backtrace (warp 0) ----------------
        int s = bi, tt = NF - 1;
        while (tt > 0) {
            unsigned short pt = sm->ptab[s];
            int f = pt >> 2;
            if (f) {
                // first state: recompute argmax_i (first occurrence), exact-bit
                f -= 1;
                int b = f / T, j = f - b * T;
                float bvv = SENT; int bii = 0x7fffffff;
                for (int i = lane; i < T; i += 32) {
                    float x = g_hist[tt * CH + b * T + i] + sm->lt[i * T + j];
                    if (x > bvv || (x == bvv && i < bii)) { bvv = x; bii = i; }
                }
                #pragma unroll
                for (int off = 16; off; off >>= 1) {
                    float xv = __shfl_down_sync(0xffffffffu, bvv, off);
                    int   xi = __shfl_down_sync(0xffffffffu, bii, off);
                    if (xv > bvv || (xv == bvv && xi < bii)) { bvv = xv; bii = xi; }
                }
                bii = __shfl_sync(0xffffffffu, bii, 0);
                int p = sm->plsm[b * T + bii];
                if (lane == 0) out[tt - 1] = (float)p;
                s = p; tt -= 1;
            } else {
                // emit a chain run (up to 32 entries at once)
                int ss = s - 1 - lane;
                bool isf = (ss >= 0) ? ((sm->ptab[ss] >> 2) != 0) : true;
                unsigned flags = __ballot_sync(0xffffffffu, isf);
                int cnt = flags ? __ffs(flags) : 32;   // include the first-state entry
                cnt = min(cnt, tt);
                if (lane < cnt) out[tt - 1 - lane] = (float)(s - 1 - lane);
                s -= cnt; tt -= cnt;
            }
        }
    }
}

extern "C" void kernel_launch(void* const* d_in, const int* in_sizes, int n_in,
                              void* d_out, int out_size)
{
    const float* acts = (const float*)d_in[0];
    const float* lt   = (const float*)d_in[1];
    const int*   pl   = (const int*)d_in[2];
    const int*   fs   = (const int*)d_in[3];
    const int*   ptr  = (const int*)d_in[4];

    int NF = in_sizes[0] / 2;          // activations (NF, 2)
    int T  = in_sizes[2] / 4;          // prev_last (4, T)
    int S  = in_sizes[4];              // pointer (S,)
    if (NF > NFMAX) NF = NFMAX;

    size_t smem = sizeof(SM);
    static bool attr_set = false;
    if (!attr_set) {
        cudaFuncSetAttribute(dbn_viterbi_kernel,
                             cudaFuncAttributeMaxDynamicSharedMemorySize, (int)smem);
        attr_set = true;
    }
    dbn_viterbi_kernel<<<1, NTH, smem>>>(acts, lt, pl, fs, ptr,
                                         (float*)d_out, S, T, NF, out_size);
}

// round 6
// speedup vs baseline: 3.8716x; 3.8533x over previous
#include <cuda_runtime.h>

#define NTH   512
#define CAPV  16384
#define CH    256
#define SPT   3
#define SLCAP 4096
#define SENT  (-1e38f)
#define NEGV  (-1e30f)
#define NFMAX 6000

// shared-memory float offsets
#define OFF_RAW0  0              // 16392 floats (guard at [3], V0 = +4)
#define OFF_RAW1  16392          // 16392 floats (guard at [3], V1 = +4)
#define OFF_LT    32784          // 4096
#define OFF_DENS  36880          // 18000  (overlaid by rv/ri at the end)
#define OFF_CAND  54880          // 256
#define OFF_PLSM  55136          // 256
#define OFF_FMASK 55392          // 512 (uint32 bitmask of first states)
#define OFF_MISC  55904          // scount etc.
#define SM_FLOATS 55936          // 223,744 bytes

__device__ float g_hist[NFMAX * CH];   // v_t[prev_last] history for backtrace

__global__ void __launch_bounds__(NTH, 1)
dbn_kernel(const float* __restrict__ acts,
           const float* __restrict__ log_trans,
           const int*   __restrict__ prev_last,
           const int*   __restrict__ first_states,
           const int*   __restrict__ pointer,
           float*       __restrict__ out,
           int S, int T, int NF, int out_size)
{
    extern __shared__ float smf[];
    float* V0   = smf + OFF_RAW0 + 4;
    float* V1   = smf + OFF_RAW1 + 4;
    float* lt   = smf + OFF_LT;
    float* dens = smf + OFF_DENS;
    float* cand = smf + OFF_CAND;
    int*   plsm = (int*)(smf + OFF_PLSM);
    unsigned* fmask = (unsigned*)(smf + OFF_FMASK);
    int*   scount = (int*)(smf + OFF_MISC);

    const int tid  = threadIdx.x;
    const int lane = tid & 31;
    const int wid  = tid >> 5;
    const int NT4  = 4 * T;

    // ---------------- setup ----------------
    for (int i = tid; i < T * T; i += NTH) lt[i] = log_trans[i];
    if (tid < NT4) plsm[tid] = prev_last[tid];
    for (int i = tid; i < 512; i += NTH) fmask[i] = 0u;
    for (int i = tid; i < 256; i += NTH) cand[i] = 0.f;   // pad slots stay 0 forever
    if (tid == 0) *scount = 0;
    __syncthreads();

    if (tid < NT4) {
        int fs = first_states[tid];
        atomicOr(&fmask[fs >> 5], 1u << (fs & 31));
    }
    __syncthreads();

    // sparse exception list (ptr!=0, not a first state) — overlay on raw1
    int* slist = (int*)(smf + OFF_RAW1);
    for (int s = tid; s < S; s += NTH) {
        int p = pointer[s];
        if (p != 0 && !((fmask[s >> 5] >> (s & 31)) & 1u)) {
            int pos = atomicAdd(scount, 1);
            if (pos < SLCAP) slist[pos] = (s << 2) | p;
        }
    }
    __syncthreads();

    int ns = min(*scount, SLCAP);
    int   sp_s[SPT];  bool sp_d2[SPT];  float pend_sp[SPT];
    #pragma unroll
    for (int e = 0; e < SPT; e++) {
        int idx = tid + e * NTH;
        if (idx < ns) { int v = slist[idx]; sp_s[e] = v >> 2; sp_d2[e] = ((v & 3) == 2); }
        else          { sp_s[e] = -1;       sp_d2[e] = false; }
        pend_sp[e] = 0.f;
    }
    __syncthreads();   // slist consumed; raw1 region free again

    // init V0, guards, and ALL frame densities (off the per-frame critical path)
    {
        float v0i = -logf((float)S);
        for (int s = tid; s < CAPV; s += NTH) V0[s] = v0i;
        if (tid == 0) { V0[-1] = NEGV; V1[-1] = NEGV; }
        for (int f = tid; f < NF; f += NTH) {
            float ab = acts[2 * f], ad = acts[2 * f + 1];
            dens[3 * f + 0] = logf((1.f - ab - ad) * (1.f / 15.f));
            dens[3 * f + 1] = logf(ab);
            dens[3 * f + 2] = logf(ad);
        }
    }

    // transition roles: 2 threads per (beat,tempo-j); lt slice kept in registers
    const bool isA = (tid < 2 * NT4);
    const int  task  = tid >> 1;
    const int  cpart = tid & 1;
    int a_b = 0, a_j = 0, a_faddr = 0;
    bool a_beat0 = false;
    if (isA) {
        a_b = task / T; a_j = task - a_b * T;
        a_faddr = first_states[task];
        a_beat0 = (a_b == 0);
    }
    __syncthreads();   // V0 + dens ready; lt ready

    float ltreg[32];
    #pragma unroll
    for (int k = 0; k < 32; k++) {
        int i = cpart * 32 + k;
        ltreg[k] = (isA && i < T) ? lt[i * T + a_j] : SENT;
    }
    const int candbase = a_b * 64 + cpart * 32;

    int my_pl = (tid < NT4) ? plsm[tid] : 0;
    int my_coff = 0;
    if (tid < NT4) { int b = tid / T, i = tid - b * T; my_coff = b * 64 + i; }

    const int dw0 = wid << 10;    // dense base word for this warp
    const int dL4 = lane << 2;
    float pend_first = 0.f;

    // ---------------- forward Viterbi: 2 barriers / frame ----------------
    for (int t = 0; t < NF; t++) {
        float* Vc = (t & 1) ? V1 : V0;    // v_t
        float* Vn = (t & 1) ? V0 : V1;    // v_{t+1}

        // phase-1: apply pending exception values into v_t; stage cand + history
        if (t > 0) {
            if (isA && cpart == 0) Vc[a_faddr] = pend_first;
            #pragma unroll
            for (int e = 0; e < SPT; e++)
                if (sp_s[e] >= 0) Vc[sp_s[e]] = pend_sp[e];
        }
        if (tid < NT4) {
            float cv = Vc[my_pl];
            cand[my_coff] = cv;
            g_hist[t * CH + tid] = cv;
        }
        __syncthreads();

        // phase-2: all reads from Vc, dense writes to Vn, exceptions to registers
        float d0 = dens[3 * t], d1 = dens[3 * t + 1], d2 = dens[3 * t + 2];

        #pragma unroll
        for (int g = 0; g < 8; g++) {
            int idx = dw0 + (g << 7) + dL4;        // conflict-free float4
            float4 A = *(const float4*)(Vc + idx);
            float pm = Vc[idx - 1];
            float4 o;
            o.x = pm  + d0; o.y = A.x + d0; o.z = A.y + d0; o.w = A.z + d0;
            *(float4*)(Vn + idx) = o;
        }

        if (isA) {
            float acc0 = SENT, acc1 = SENT, acc2 = SENT, acc3 = SENT;
            const float4* cb = (const float4*)(cand + candbase);
            #pragma unroll
            for (int q = 0; q < 8; q++) {
                float4 cv = cb[q];
                acc0 = fmaxf(acc0, cv.x + ltreg[4 * q + 0]);
                acc1 = fmaxf(acc1, cv.y + ltreg[4 * q + 1]);
                acc2 = fmaxf(acc2, cv.z + ltreg[4 * q + 2]);
                acc3 = fmaxf(acc3, cv.w + ltreg[4 * q + 3]);
            }
            float acc = fmaxf(fmaxf(acc0, acc1), fmaxf(acc2, acc3));
            float other = __shfl_down_sync(0xffffffffu, acc, 1);
            pend_first = fmaxf(acc, other) + (a_beat0 ? d2 : d1);
        }
        #pragma unroll
        for (int e = 0; e < SPT; e++)
            if (sp_s[e] >= 0)
                pend_sp[e] = Vc[sp_s[e] - 1] + (sp_d2[e] ? d2 : d1);

        __syncthreads();
    }

    // ---------------- apply final fixups, argmax, backtrace ----------------
    float* Vf = (NF & 1) ? V1 : V0;       // v_NF
    float* Vd = (NF & 1) ? V0 : V1;       // dead buffer (fof overlay)
    if (isA && cpart == 0) Vf[a_faddr] = pend_first;
    #pragma unroll
    for (int e = 0; e < SPT; e++)
        if (sp_s[e] >= 0) Vf[sp_s[e]] = pend_sp[e];
    __syncthreads();

    float* rv = dens;                      // overlays (dens no longer needed)
    int*   ri = (int*)(dens + NTH);
    int*   fof = (int*)Vd;
    if (isA && cpart == 0) fof[a_faddr] = task;
    {
        float bv = SENT; int bi = 0;
        #pragma unroll
        for (int k = 0; k < CAPV / NTH; k++) {
            int s = tid * (CAPV / NTH) + k;
            if (s < S) { float x = Vf[s]; if (x > bv) { bv = x; bi = s; } }
        }
        rv[tid] = bv; ri[tid] = bi;
    }
    __syncthreads();

    if (wid == 0) {
        float bv = SENT; int bi = 0x7fffffff;
        for (int m = lane; m < NTH; m += 32) {
            float x = rv[m]; int ii = ri[m];
            if (x > bv || (x == bv && ii < bi)) { bv = x; bi = ii; }
        }
        #pragma unroll
        for (int off = 16; off; off >>= 1) {
            float xv = __shfl_down_sync(0xffffffffu, bv, off);
            int   xi = __shfl_down_sync(0xffffffffu, bi, off);
            if (xv > bv || (xv == bv && xi < bi)) { bv = xv; bi = xi; }
        }
        bi = __shfl_sync(0xffffffffu, bi, 0);
        bv = __shfl_sync(0xffffffffu, bv, 0);
        if (lane == 0) {
            if (out_size > NF) out[NF] = bv;   // logp
            out[NF - 1] = (float)bi;           // path[NF-1]
        }

        int s = bi, tt = NF - 1;
        while (tt > 0) {
            bool isf = (fmask[s >> 5] >> (s & 31)) & 1u;
            if (isf) {
                int f = fof[s];
                int b = f / T, j = f - b * T;
                float bvv = SENT; int bii = 0x7fffffff;
                for (int i = lane; i < T; i += 32) {
                    float x = g_hist[tt * CH + b * T + i] + lt[i * T + j];
                    if (x > bvv || (x == bvv && i < bii)) { bvv = x; bii = i; }
                }
                #pragma unroll
                for (int off = 16; off; off >>= 1) {
                    float xv = __shfl_down_sync(0xffffffffu, bvv, off);
                    int   xi = __shfl_down_sync(0xffffffffu, bii, off);
                    if (xv > bvv || (xv == bvv && xi < bii)) { bvv = xv; bii = xi; }
                }
                bii = __shfl_sync(0xffffffffu, bii, 0);
                int p = plsm[b * T + bii];
                if (lane == 0) out[tt - 1] = (float)p;
                s = p; tt -= 1;
            } else {
                int ss = s - 1 - lane;
                bool ef = (ss < 0) ? true : (((fmask[ss >> 5] >> (ss & 31)) & 1u) != 0);
                unsigned flags = __ballot_sync(0xffffffffu, ef);
                int cnt = flags ? __ffs(flags) : 32;
                cnt = min(cnt, tt);
                if (lane < cnt) out[tt - 1 - lane] = (float)(s - 1 - lane);
                s -= cnt; tt -= cnt;
            }
        }
    }
}

extern "C" void kernel_launch(void* const* d_in, const int* in_sizes, int n_in,
                              void* d_out, int out_size)
{
    const float* acts = (const float*)d_in[0];
    const float* ltg  = (const float*)d_in[1];
    const int*   pl   = (const int*)d_in[2];
    const int*   fs   = (const int*)d_in[3];
    const int*   ptr  = (const int*)d_in[4];

    int NF = in_sizes[0] / 2;
    int T  = in_sizes[2] / 4;
    int S  = in_sizes[4];
    if (NF > NFMAX) NF = NFMAX;

    size_t smem = (size_t)SM_FLOATS * sizeof(float);
    static bool attr_set = false;
    if (!attr_set) {
        cudaFuncSetAttribute(dbn_kernel,
                             cudaFuncAttributeMaxDynamicSharedMemorySize, (int)smem);
        attr_set = true;
    }
    dbn_kernel<<<1, NTH, smem>>>(acts, ltg, pl, fs, ptr,
                                 (float*)d_out, S, T, NF, out_size);
}

// round 7
// speedup vs baseline: 3.9073x; 1.0092x over previous
#include <cuda_runtime.h>

#define NTH   512
#define CAPV  16384
#define CH    256
#define SPT   3
#define SLCAP 4096
#define SENT  (-1e38f)
#define NEGV  (-1e30f)
#define NFMAX 6000

// shared-memory float offsets
#define OFF_RAW0  0              // 16392 floats (guard at [3], V0 = +4)
#define OFF_RAW1  16392          // 16392 floats (guard at [3], V1 = +4)
#define OFF_LT    32784          // 4096
#define OFF_DENS  36880          // 18000  (overlaid by rv/ri at the end)
#define OFF_CAND  54880          // 256
#define OFF_PLSM  55136          // 256
#define OFF_FMASK 55392          // 512 (uint32 bitmask of first states)
#define OFF_MISC  55904          // scount etc.
#define SM_FLOATS 55936          // 223,744 bytes

__device__ float g_hist[NFMAX * CH];   // v_t[prev_last] history for backtrace

__global__ void __launch_bounds__(NTH, 1)
dbn_kernel(const float* __restrict__ acts,
           const float* __restrict__ log_trans,
           const int*   __restrict__ prev_last,
           const int*   __restrict__ first_states,
           const int*   __restrict__ pointer,
           float*       __restrict__ out,
           int S, int T, int NF, int out_size)
{
    extern __shared__ float smf[];
    float* V0   = smf + OFF_RAW0 + 4;
    float* V1   = smf + OFF_RAW1 + 4;
    float* lt   = smf + OFF_LT;
    float* dens = smf + OFF_DENS;
    float* cand = smf + OFF_CAND;
    int*   plsm = (int*)(smf + OFF_PLSM);
    unsigned* fmask = (unsigned*)(smf + OFF_FMASK);
    int*   scount = (int*)(smf + OFF_MISC);

    const int tid  = threadIdx.x;
    const int lane = tid & 31;
    const int wid  = tid >> 5;
    const int NT4  = 4 * T;

    // ---------------- setup ----------------
    for (int i = tid; i < T * T; i += NTH) lt[i] = log_trans[i];
    if (tid < NT4) plsm[tid] = prev_last[tid];
    for (int i = tid; i < 512; i += NTH) fmask[i] = 0u;
    for (int i = tid; i < 256; i += NTH) cand[i] = 0.f;   // pad slots stay 0 forever
    if (tid == 0) *scount = 0;
    __syncthreads();

    if (tid < NT4) {
        int fs = first_states[tid];
        atomicOr(&fmask[fs >> 5], 1u << (fs & 31));
    }
    __syncthreads();

    // sparse exception list (ptr!=0, not a first state) — overlay on raw1
    int* slist = (int*)(smf + OFF_RAW1);
    for (int s = tid; s < S; s += NTH) {
        int p = pointer[s];
        if (p != 0 && !((fmask[s >> 5] >> (s & 31)) & 1u)) {
            int pos = atomicAdd(scount, 1);
            if (pos < SLCAP) slist[pos] = (s << 2) | p;
        }
    }
    __syncthreads();

    int ns = min(*scount, SLCAP);
    int   sp_s[SPT];  bool sp_d2[SPT];  float pend_sp[SPT];
    #pragma unroll
    for (int e = 0; e < SPT; e++) {
        int idx = tid + e * NTH;
        if (idx < ns) { int v = slist[idx]; sp_s[e] = v >> 2; sp_d2[e] = ((v & 3) == 2); }
        else          { sp_s[e] = -1;       sp_d2[e] = false; }
        pend_sp[e] = 0.f;
    }
    __syncthreads();   // slist consumed; raw1 region free again

    // init V0, guards, and ALL frame densities (off the per-frame critical path)
    {
        float v0i = -logf((float)S);
        for (int s = tid; s < CAPV; s += NTH) V0[s] = v0i;
        if (tid == 0) { V0[-1] = NEGV; V1[-1] = NEGV; }
        for (int f = tid; f < NF; f += NTH) {
            float ab = acts[2 * f], ad = acts[2 * f + 1];
            dens[3 * f + 0] = logf((1.f - ab - ad) * (1.f / 15.f));
            dens[3 * f + 1] = logf(ab);
            dens[3 * f + 2] = logf(ad);
        }
    }

    // transition roles: 2 threads per (beat,tempo-j); lt slice kept in registers
    const bool isA = (tid < 2 * NT4);
    const int  task  = tid >> 1;
    const int  cpart = tid & 1;
    int a_b = 0, a_j = 0, a_faddr = 0;
    bool a_beat0 = false;
    if (isA) {
        a_b = task / T; a_j = task - a_b * T;
        a_faddr = first_states[task];
        a_beat0 = (a_b == 0);
    }
    __syncthreads();   // V0 + dens ready; lt ready

    float ltreg[32];
    #pragma unroll
    for (int k = 0; k < 32; k++) {
        int i = cpart * 32 + k;
        ltreg[k] = (isA && i < T) ? lt[i * T + a_j] : SENT;
    }
    const int candbase = a_b * 64 + cpart * 32;

    int my_pl = (tid < NT4) ? plsm[tid] : 0;
    int my_coff = 0;
    if (tid < NT4) { int b = tid / T, i = tid - b * T; my_coff = b * 64 + i; }

    const int dw0 = wid << 10;    // dense base word for this warp
    const int dL4 = lane << 2;
    float pend_first = 0.f;

    // ---------------- forward Viterbi: 2 barriers / frame ----------------
    for (int t = 0; t < NF; t++) {
        float* Vc = (t & 1) ? V1 : V0;    // v_t
        float* Vn = (t & 1) ? V0 : V1;    // v_{t+1}

        // phase-1: apply pending exception values into v_t; stage cand + history
        if (t > 0) {
            if (isA && cpart == 0) Vc[a_faddr] = pend_first;
            #pragma unroll
            for (int e = 0; e < SPT; e++)
                if (sp_s[e] >= 0) Vc[sp_s[e]] = pend_sp[e];
        }
        if (tid < NT4) {
            float cv = Vc[my_pl];
            cand[my_coff] = cv;
            g_hist[t * CH + tid] = cv;
        }
        __syncthreads();

        // phase-2: all reads from Vc, dense writes to Vn, exceptions to registers
        float d0 = dens[3 * t], d1 = dens[3 * t + 1], d2 = dens[3 * t + 2];

        #pragma unroll
        for (int g = 0; g < 8; g++) {
            int idx = dw0 + (g << 7) + dL4;        // conflict-free float4
            float4 A = *(const float4*)(Vc + idx);
            float pm = Vc[idx - 1];
            float4 o;
            o.x = pm  + d0; o.y = A.x + d0; o.z = A.y + d0; o.w = A.z + d0;
            *(float4*)(Vn + idx) = o;
        }

        if (isA) {
            float acc0 = SENT, acc1 = SENT, acc2 = SENT, acc3 = SENT;
            const float4* cb = (const float4*)(cand + candbase);
            #pragma unroll
            for (int q = 0; q < 8; q++) {
                float4 cv = cb[q];
                acc0 = fmaxf(acc0, cv.x + ltreg[4 * q + 0]);
                acc1 = fmaxf(acc1, cv.y + ltreg[4 * q + 1]);
                acc2 = fmaxf(acc2, cv.z + ltreg[4 * q + 2]);
                acc3 = fmaxf(acc3, cv.w + ltreg[4 * q + 3]);
            }
            float acc = fmaxf(fmaxf(acc0, acc1), fmaxf(acc2, acc3));
            float other = __shfl_down_sync(0xffffffffu, acc, 1);
            pend_first = fmaxf(acc, other) + (a_beat0 ? d2 : d1);
        }
        #pragma unroll
        for (int e = 0; e < SPT; e++)
            if (sp_s[e] >= 0)
                pend_sp[e] = Vc[sp_s[e] - 1] + (sp_d2[e] ? d2 : d1);

        __syncthreads();
    }

    // ---------------- apply final fixups, argmax, backtrace ----------------
    float* Vf = (NF & 1) ? V1 : V0;       // v_NF
    float* Vd = (NF & 1) ? V0 : V1;       // dead buffer (fof overlay)
    if (isA && cpart == 0) Vf[a_faddr] = pend_first;
    #pragma unroll
    for (int e = 0; e < SPT; e++)
        if (sp_s[e] >= 0) Vf[sp_s[e]] = pend_sp[e];
    __syncthreads();

    float* rv = dens;                      // overlays (dens no longer needed)
    int*   ri = (int*)(dens + NTH);
    int*   fof = (int*)Vd;
    if (isA && cpart == 0) fof[a_faddr] = task;
    {
        float bv = SENT; int bi = 0;
        #pragma unroll
        for (int k = 0; k < CAPV / NTH; k++) {
            int s = tid * (CAPV / NTH) + k;
            if (s < S) { float x = Vf[s]; if (x > bv) { bv = x; bi = s; } }
        }
        rv[tid] = bv; ri[tid] = bi;
    }
    __syncthreads();

    if (wid == 0) {
        float bv = SENT; int bi = 0x7fffffff;
        for (int m = lane; m < NTH; m += 32) {
            float x = rv[m]; int ii = ri[m];
            if (x > bv || (x == bv && ii < bi)) { bv = x; bi = ii; }
        }
        #pragma unroll
        for (int off = 16; off; off >>= 1) {
            float xv = __shfl_down_sync(0xffffffffu, bv, off);
            int   xi = __shfl_down_sync(0xffffffffu, bi, off);
            if (xv > bv || (xv == bv && xi < bi)) { bv = xv; bi = xi; }
        }
        bi = __shfl_sync(0xffffffffu, bi, 0);
        bv = __shfl_sync(0xffffffffu, bv, 0);
        if (lane == 0) {
            if (out_size > NF) out[NF] = bv;   // logp
            out[NF - 1] = (float)bi;           // path[NF-1]
        }

        int s = bi, tt = NF - 1;
        while (tt > 0) {
            bool isf = (fmask[s >> 5] >> (s & 31)) & 1u;
            if (isf) {
                int f = fof[s];
                int b = f / T, j = f - b * T;
                float bvv = SENT; int bii = 0x7fffffff;
                for (int i = lane; i < T; i += 32) {
                    float x = g_hist[tt * CH + b * T + i] + lt[i * T + j];
                    if (x > bvv || (x == bvv && i < bii)) { bvv = x; bii = i; }
                }
                #pragma unroll
                for (int off = 16; off; off >>= 1) {
                    float xv = __shfl_down_sync(0xffffffffu, bvv, off);
                    int   xi = __shfl_down_sync(0xffffffffu, bii, off);
                    if (xv > bvv || (xv == bvv && xi < bii)) { bvv = xv; bii = xi; }
                }
                bii = __shfl_sync(0xffffffffu, bii, 0);
                int p = plsm[b * T + bii];
                if (lane == 0) out[tt - 1] = (float)p;
                s = p; tt -= 1;
            } else {
                int ss = s - 1 - lane;
                bool ef = (ss < 0) ? true : (((fmask[ss >> 5] >> (ss & 31)) & 1u) != 0);
                unsigned flags = __ballot_sync(0xffffffffu, ef);
                int cnt = flags ? __ffs(flags) : 32;
                cnt = min(cnt, tt);
                if (lane < cnt) out[tt - 1 - lane] = (float)(s - 1 - lane);
                s -= cnt; tt -= cnt;
            }
        }
    }
}

extern "C" void kernel_launch(void* const* d_in, const int* in_sizes, int n_in,
                              void* d_out, int out_size)
{
    const float* acts = (const float*)d_in[0];
    const float* ltg  = (const float*)d_in[1];
    const int*   pl   = (const int*)d_in[2];
    const int*   fs   = (const int*)d_in[3];
    const int*   ptr  = (const int*)d_in[4];

    int NF = in_sizes[0] / 2;
    int T  = in_sizes[2] / 4;
    int S  = in_sizes[4];
    if (NF > NFMAX) NF = NFMAX;

    size_t smem = (size_t)SM_FLOATS * sizeof(float);
    static bool attr_set = false;
    if (!attr_set) {
        cudaFuncSetAttribute(dbn_kernel,
                             cudaFuncAttributeMaxDynamicSharedMemorySize, (int)smem);
        attr_set = true;
    }
    dbn_kernel<<<1, NTH, smem>>>(acts, ltg, pl, fs, ptr,
                                 (float*)d_out, S, T, NF, out_size);
}

// round 8
// speedup vs baseline: 7.0224x; 1.7973x over previous
#include <cuda_runtime.h>

#define NTH   512
#define CAPV  16384
#define CH    256
#define ENT   4
#define ELCAP 2048
#define SENT  (-1e38f)
#define NEGV  (-1e30f)
#define NFMAX 6000

// shared-memory float offsets
#define OFF_RAW0  0              // 16392: guard [0..3], V0 = +4
#define OFF_RAW1  16392          // 16392: guard [0..3], V1 = +4
#define OFF_LT    32784          // 4096
#define OFF_DENS  36880          // 18000 (rv/ri overlay at end)
#define OFF_CANDM 54880          // 4*256: cand_m at m*256 + b*64 + i
#define OFF_TBUF  55904          // 4*256: T_m at m*256 + task
#define OFF_PLSM  56928          // 256
#define OFF_FMASK 57184          // 512 uints (first-state bitmask)
#define OFF_MISC  57696          // 64
#define SM_FLOATS 57760          // 231,040 B

__device__ float g_hist[NFMAX * CH];   // v_t[prev_last] history for backtrace

typedef unsigned long long u64;
__device__ __forceinline__ u64 pk2(float a, float b) {
    u64 r; asm("mov.b64 %0,{%1,%2};" : "=l"(r) : "f"(a), "f"(b)); return r;
}
__device__ __forceinline__ void upk2(u64 p, float& a, float& b) {
    asm("mov.b64 {%0,%1},%2;" : "=f"(a), "=f"(b) : "l"(p));
}
__device__ __forceinline__ u64 padd2(u64 a, u64 b) {
    u64 r; asm("add.rn.f32x2 %0, %1, %2;" : "=l"(r) : "l"(a), "l"(b)); return r;
}

// classify state s for the fused-4 update. Returns 1 + meta/start if exceptional.
__device__ __forceinline__ int classify(int s, const int* __restrict__ ptr,
                                        const unsigned* fmask, const int* fof0,
                                        int* meta, int* start)
{
    int r = -1;
    #pragma unroll
    for (int k = 0; k < 4; k++) {
        int x = s - k;
        if (r < 0 && x >= 0 && ((fmask[x >> 5] >> (x & 31)) & 1u)) r = k;
    }
    if (r >= 0) {   // within 3 of a first state f = s-r
        int f = s - r, j = fof0[f], m0 = 3 - r;
        unsigned codes = 0;
        #pragma unroll
        for (int m = 0; m < 4; m++) {
            unsigned c = (m < m0) ? 3u : (unsigned)__ldg(ptr + (f + (m - m0)));
            codes |= c << (2 * m);
        }
        *meta  = s | (1 << 14) | ((int)codes << 16);
        *start = (m0 << 8) + j;          // Tbuf index
        return 1;
    }
    unsigned codes = 0; int nz = 0;
    #pragma unroll
    for (int m = 0; m < 4; m++) {
        unsigned c = (unsigned)__ldg(ptr + (s - 3 + m));
        codes |= c << (2 * m);
        nz |= (c != 0u);
    }
    if (!nz) return 0;                   // clean dense state
    *meta  = s | ((int)codes << 16);
    *start = s - 4;                      // Vc index
    return 1;
}

__global__ void __launch_bounds__(NTH, 1)
dbn_kernel(const float* __restrict__ acts,
           const float* __restrict__ log_trans,
           const int*   __restrict__ prev_last,
           const int*   __restrict__ first_states,
           const int*   __restrict__ pointer,
           float*       __restrict__ out,
           int S, int T, int NF, int out_size)
{
    extern __shared__ float smf[];
    float* V0    = smf + OFF_RAW0 + 4;
    float* V1    = smf + OFF_RAW1 + 4;
    float* lt    = smf + OFF_LT;
    float* dens  = smf + OFF_DENS;
    float* candm = smf + OFF_CANDM;
    float* Tsm   = smf + OFF_TBUF;
    int*   plsm  = (int*)(smf + OFF_PLSM);
    unsigned* fmask = (unsigned*)(smf + OFF_FMASK);
    int*   misc  = (int*)(smf + OFF_MISC);

    const int tid  = threadIdx.x;
    const int lane = tid & 31;
    const int wid  = tid >> 5;
    const int NT4  = 4 * T;

    // ---------------- setup: tables ----------------
    for (int i = tid; i < T * T; i += NTH) lt[i] = log_trans[i];
    if (tid < NT4) plsm[tid] = prev_last[tid];
    for (int i = tid; i < 512; i += NTH) fmask[i] = 0u;
    for (int i = tid; i < 1024; i += NTH) candm[i] = 0.f;   // pads stay 0
    __syncthreads();

    int* fof0 = (int*)(smf + OFF_RAW0);      // setup overlay on V0 region
    if (tid < NT4) {
        int fs = first_states[tid];
        atomicOr(&fmask[fs >> 5], 1u << (fs & 31));
        fof0[fs] = tid;
    }
    __syncthreads();

    // ---------------- setup: exception entries (deterministic scan) ----------------
    int cnt = 0;
    for (int k = 0; k < 32; k++) {
        int s = (tid << 5) + k;
        if (s < S) { int mt, stx; cnt += classify(s, pointer, fmask, fof0, &mt, &stx); }
    }
    int inc = cnt;
    #pragma unroll
    for (int off = 1; off < 32; off <<= 1) {
        int n = __shfl_up_sync(0xffffffffu, inc, off);
        if (lane >= off) inc += n;
    }
    int* wtot = misc + 8;
    if (lane == 31) wtot[wid] = inc;
    __syncthreads();
    if (tid == 0) {
        int acc = 0;
        for (int w = 0; w < 16; w++) { int tw = wtot[w]; wtot[w] = acc; acc += tw; }
        misc[0] = acc;
    }
    __syncthreads();
    int base = wtot[wid] + inc - cnt;
    int* ex = (int*)(smf + OFF_RAW1);        // setup overlay on V1 region
    int* ey = ex + ELCAP;
    for (int k = 0; k < 32; k++) {
        int s = (tid << 5) + k;
        if (s < S) {
            int mt, stx;
            if (classify(s, pointer, fmask, fof0, &mt, &stx)) {
                if (base < ELCAP) { ex[base] = mt; ey[base] = stx; }
                base++;
            }
        }
    }
    __syncthreads();
    int nent = min(misc[0], ELCAP);
    int ems[ENT], eys[ENT];
    {
        int eb = (NTH - 1 - tid) * ENT;      // contiguous chunks, high tids first
        #pragma unroll
        for (int e = 0; e < ENT; e++) {
            int ix = eb + e;
            if (ix >= 0 && ix < nent) { ems[e] = ex[ix]; eys[e] = ey[ix]; }
            else                       { ems[e] = -1;     eys[e] = 0; }
        }
    }
    __syncthreads();                         // overlays dead; V0/V1 free

    // ---------------- setup: V0, guards, densities ----------------
    {
        float v0i = -logf((float)S);
        for (int s = tid; s < CAPV; s += NTH) V0[s] = v0i;
        if (tid < 4) { smf[OFF_RAW0 + tid] = NEGV; smf[OFF_RAW1 + tid] = NEGV; }
        for (int f = tid; f < NF; f += NTH) {
            float ab = acts[2 * f], ad = acts[2 * f + 1];
            dens[3 * f + 0] = logf((1.f - ab - ad) * (1.f / 15.f));
            dens[3 * f + 1] = logf(ab);
            dens[3 * f + 2] = logf(ad);
        }
    }

    // transition roles: 2 threads per task, lt window in registers
    const bool isA  = (tid < 2 * NT4);
    const int  task  = tid >> 1;
    const int  cpart = tid & 1;
    int a_b = 0, a_faddr = 0, a_fc = 1;
    if (isA) {
        a_b = task / T;
        a_faddr = __ldg(first_states + task);
        a_fc = __ldg(pointer + a_faddr);     // 2 for beat0, else 1
    }
    __syncthreads();                         // lt ready for ltreg loads; V0/dens ready

    float ltreg[32];
    bool skip = !isA;
    {
        int a_j = task - a_b * T;
        float mx = SENT;
        #pragma unroll
        for (int k = 0; k < 32; k++) {
            int i = cpart * 32 + k;
            float v = (isA && i < T) ? lt[i * T + a_j] : SENT;
            ltreg[k] = v;
            mx = fmaxf(mx, v);
        }
        if (mx < -1e28f) skip = true;        // fully out-of-band half → skip
    }
    const int candbase = (a_b << 6) + (cpart << 5);

    // staging role: tid in [256, 256+NT4)
    const int st = tid - 256;
    const bool stOK = (st >= 0 && st < NT4);
    int my_pl = 0, coff = 0;
    if (stOK) { my_pl = plsm[st]; int b = st / T; coff = (b << 6) + (st - b * T); }

    const int dw0 = wid << 10;
    const int dL4 = lane << 2;

    int rem = NF & 3;
    int NFf = NF - rem;

    // pre-stage cand_0..3 from V0 (frames 0..3)
    if (NFf > 0 && stOK) {
        float e0 = dens[0], e1 = dens[3], e2 = dens[6];
        float c0 = V0[my_pl];
        float c1 = V0[my_pl - 1] + e0;
        float c2 = (V0[my_pl - 2] + e0) + e1;
        float c3 = ((V0[my_pl - 3] + e0) + e1) + e2;
        candm[coff] = c0; candm[256 + coff] = c1;
        candm[512 + coff] = c2; candm[768 + coff] = c3;
        g_hist[0 * CH + st] = c0; g_hist[1 * CH + st] = c1;
        g_hist[2 * CH + st] = c2; g_hist[3 * CH + st] = c3;
    }

    float* Vbuf0 = V0; float* Vbuf1 = V1;
    int cur = 0;

    // ---------------- fused-4 forward loop: 2 barriers / 4 frames ----------------
    for (int t = 0; t < NFf; t += 4) {
        float* Vc = cur ? Vbuf1 : Vbuf0;
        float* Vn = cur ? Vbuf0 : Vbuf1;
        __syncthreads();   // cand staged + exceptions applied to Vc

        float dd[4][3];
        #pragma unroll
        for (int m = 0; m < 4; m++) {
            dd[m][0] = dens[3 * (t + m) + 0];
            dd[m][1] = dens[3 * (t + m) + 1];
            dd[m][2] = dens[3 * (t + m) + 2];
        }
        u64 D0 = pk2(dd[0][0], dd[0][0]);
        u64 D1 = pk2(dd[1][0], dd[1][0]);
        u64 D2 = pk2(dd[2][0], dd[2][0]);
        u64 D3 = pk2(dd[3][0], dd[3][0]);

        // dense: v_{t+4}[s] = v_t[s-4] + d0(t)+d0(t+1)+d0(t+2)+d0(t+3), packed f32x2
        #pragma unroll
        for (int g = 0; g < 8; g++) {
            int idx = dw0 + (g << 7) + dL4;
            float4 A = *(const float4*)(Vc + idx - 4);
            u64 p0 = pk2(A.x, A.y), p1 = pk2(A.z, A.w);
            p0 = padd2(p0, D0); p1 = padd2(p1, D0);
            p0 = padd2(p0, D1); p1 = padd2(p1, D1);
            p0 = padd2(p0, D2); p1 = padd2(p1, D2);
            p0 = padd2(p0, D3); p1 = padd2(p1, D3);
            float4 o; upk2(p0, o.x, o.y); upk2(p1, o.z, o.w);
            *(float4*)(Vn + idx) = o;
        }

        // transitions: T_m[task] = max_i cand_m[i] + lt[i][j], 4 frames
        float am[4] = {SENT, SENT, SENT, SENT};
        if (!skip) {
            #pragma unroll
            for (int m = 0; m < 4; m++) {
                const float4* c4 = (const float4*)(candm + (m << 8) + candbase);
                float a0 = SENT, a1 = SENT, a2 = SENT, a3 = SENT;
                #pragma unroll
                for (int q = 0; q < 8; q++) {
                    float4 cv = c4[q];
                    a0 = fmaxf(a0, cv.x + ltreg[4 * q + 0]);
                    a1 = fmaxf(a1, cv.y + ltreg[4 * q + 1]);
                    a2 = fmaxf(a2, cv.z + ltreg[4 * q + 2]);
                    a3 = fmaxf(a3, cv.w + ltreg[4 * q + 3]);
                }
                am[m] = fmaxf(fmaxf(a0, a1), fmaxf(a2, a3));
            }
        }
        #pragma unroll
        for (int m = 0; m < 4; m++) {
            float o = __shfl_down_sync(0xffffffffu, am[m], 1);
            if (isA && cpart == 0) Tsm[(m << 8) + task] = fmaxf(am[m], o);
        }

        __syncthreads();   // Tbuf + dense Vn visible

        // exceptions: unified start + 4 slot-coded density adds
        #pragma unroll
        for (int e = 0; e < ENT; e++) {
            int me = ems[e];
            if (me >= 0) {
                int s = me & 0x3FFF;
                int kindA = (me >> 14) & 1;
                unsigned codes = ((unsigned)me) >> 16;
                float val = kindA ? Tsm[eys[e]] : Vc[eys[e]];
                #pragma unroll
                for (int m = 0; m < 4; m++) {
                    unsigned c = (codes >> (2 * m)) & 3u;
                    float add = (c == 0u) ? dd[m][0]
                              : (c == 1u) ? dd[m][1]
                              : (c == 2u) ? dd[m][2] : 0.f;
                    val += add;
                }
                Vn[s] = val;
            }
        }

        // stage next step's cand from Vn (pl slots are dense-written)
        if (stOK && t + 4 < NFf) {
            float e0 = dens[3 * (t + 4)], e1 = dens[3 * (t + 5)], e2 = dens[3 * (t + 6)];
            float c0 = Vn[my_pl];
            float c1 = Vn[my_pl - 1] + e0;
            float c2 = (Vn[my_pl - 2] + e0) + e1;
            float c3 = ((Vn[my_pl - 3] + e0) + e1) + e2;
            candm[coff] = c0; candm[256 + coff] = c1;
            candm[512 + coff] = c2; candm[768 + coff] = c3;
            int hb = (t + 4) * CH + st;
            g_hist[hb] = c0; g_hist[hb + CH] = c1;
            g_hist[hb + 2 * CH] = c2; g_hist[hb + 3 * CH] = c3;
        }
        cur ^= 1;
    }

    // ---------------- tail frames (NF % 4; normally 0) ----------------
    for (int t = NFf; t < NF; t++) {
        float* Vc = cur ? Vbuf1 : Vbuf0;
        float* Vn = cur ? Vbuf0 : Vbuf1;
        __syncthreads();
        if (stOK) { float cv = Vc[my_pl]; candm[coff] = cv; g_hist[t * CH + st] = cv; }
        __syncthreads();
        float d0 = dens[3 * t], d1 = dens[3 * t + 1], d2 = dens[3 * t + 2];
        #pragma unroll
        for (int g = 0; g < 8; g++) {
            int idx = dw0 + (g << 7) + dL4;
            float4 A = *(const float4*)(Vc + idx);
            float pm = Vc[idx - 1];
            float4 o; o.x = pm + d0; o.y = A.x + d0; o.z = A.y + d0; o.w = A.z + d0;
            *(float4*)(Vn + idx) = o;
        }
        float acc = SENT;
        if (!skip) {
            const float4* c4 = (const float4*)(candm + candbase);
            #pragma unroll
            for (int q = 0; q < 8; q++) {
                float4 cv = c4[q];
                acc = fmaxf(acc, cv.x + ltreg[4 * q + 0]);
                acc = fmaxf(acc, cv.y + ltreg[4 * q + 1]);
                acc = fmaxf(acc, cv.z + ltreg[4 * q + 2]);
                acc = fmaxf(acc, cv.w + ltreg[4 * q + 3]);
            }
        }
        float oth = __shfl_down_sync(0xffffffffu, acc, 1);
        __syncthreads();
        if (isA && cpart == 0) Vn[a_faddr] = fmaxf(acc, oth) + (a_fc == 2 ? d2 : d1);
        for (int k = 0; k < 32; k++) {
            int s = (tid << 5) + k;
            if (s < S) {
                int c = __ldg(pointer + s);
                if (c != 0 && !((fmask[s >> 5] >> (s & 31)) & 1u))
                    Vn[s] = Vc[s - 1] + (c == 2 ? d2 : d1);
            }
        }
        cur ^= 1;
    }
    __syncthreads();

    // ---------------- final argmax + backtrace ----------------
    float* Vf = cur ? Vbuf1 : Vbuf0;
    float* Vd = cur ? Vbuf0 : Vbuf1;
    float* rv = dens;
    int*   ri = (int*)(dens + NTH);
    int*   fof = (int*)Vd;
    if (isA && cpart == 0) fof[a_faddr] = task;
    {
        float bv = SENT; int bi = 0;
        #pragma unroll
        for (int k = 0; k < CAPV / NTH; k++) {
            int s = tid * (CAPV / NTH) + k;
            if (s < S) { float x = Vf[s]; if (x > bv) { bv = x; bi = s; } }
        }
        rv[tid] = bv; ri[tid] = bi;
    }
    __syncthreads();

    if (wid == 0) {
        float bv = SENT; int bi = 0x7fffffff;
        for (int m = lane; m < NTH; m += 32) {
            float x = rv[m]; int ii = ri[m];
            if (x > bv || (x == bv && ii < bi)) { bv = x; bi = ii; }
        }
        #pragma unroll
        for (int off = 16; off; off >>= 1) {
            float xv = __shfl_down_sync(0xffffffffu, bv, off);
            int   xi = __shfl_down_sync(0xffffffffu, bi, off);
            if (xv > bv || (xv == bv && xi < bi)) { bv = xv; bi = xi; }
        }
        bi = __shfl_sync(0xffffffffu, bi, 0);
        bv = __shfl_sync(0xffffffffu, bv, 0);
        if (lane == 0) {
            if (out_size > NF) out[NF] = bv;   // logp
            out[NF - 1] = (float)bi;           // path[NF-1]
        }

        int s = bi, tt = NF - 1;
        while (tt > 0) {
            bool isf = (fmask[s >> 5] >> (s & 31)) & 1u;
            if (isf) {
                int f = fof[s];
                int b = f / T, j = f - b * T;
                float bvv = SENT; int bii = 0x7fffffff;
                for (int i = lane; i < T; i += 32) {
                    float x = g_hist[tt * CH + b * T + i] + lt[i * T + j];
                    if (x > bvv || (x == bvv && i < bii)) { bvv = x; bii = i; }
                }
                #pragma unroll
                for (int off = 16; off; off >>= 1) {
                    float xv = __shfl_down_sync(0xffffffffu, bvv, off);
                    int   xi = __shfl_down_sync(0xffffffffu, bii, off);
                    if (xv > bvv || (xv == bvv && xi < bii)) { bvv = xv; bii = xi; }
                }
                bii = __shfl_sync(0xffffffffu, bii, 0);
                int p = plsm[b * T + bii];
                if (lane == 0) out[tt - 1] = (float)p;
                s = p; tt -= 1;
            } else {
                int ss = s - 1 - lane;
                bool ef = (ss < 0) ? true : (((fmask[ss >> 5] >> (ss & 31)) & 1u) != 0);
                unsigned flags = __ballot_sync(0xffffffffu, ef);
                int cnt2 = flags ? __ffs(flags) : 32;
                cnt2 = min(cnt2, tt);
                if (lane < cnt2) out[tt - 1 - lane] = (float)(s - 1 - lane);
                s -= cnt2; tt -= cnt2;
            }
        }
    }
}

extern "C" void kernel_launch(void* const* d_in, const int* in_sizes, int n_in,
                              void* d_out, int out_size)
{
    const float* acts = (const float*)d_in[0];
    const float* ltg  = (const float*)d_in[1];
    const int*   pl   = (const int*)d_in[2];
    const int*   fs   = (const int*)d_in[3];
    const int*   ptr  = (const int*)d_in[4];

    int NF = in_sizes[0] / 2;
    int T  = in_sizes[2] / 4;
    int S  = in_sizes[4];
    if (NF > NFMAX) NF = NFMAX;

    size_t smem = (size_t)SM_FLOATS * sizeof(float);
    static bool attr_set = false;
    if (!attr_set) {
        cudaFuncSetAttribute(dbn_kernel,
                             cudaFuncAttributeMaxDynamicSharedMemorySize, (int)smem);
        attr_set = true;
    }
    dbn_kernel<<<1, NTH, smem>>>(acts, ltg, pl, fs, ptr,
                                 (float*)d_out, S, T, NF, out_size);
}